// round 6
// baseline (speedup 1.0000x reference)
#include <cuda_runtime.h>
#include <cuda_bf16.h>

// DistortionLoss (eff_distloss) — single fused kernel, persistent single-wave.
//
// R5 -> R6: all variants pin at ~6.1 TB/s = B300 LTS chip cap (path-indep),
// so bandwidth is done; remove structural overhead instead. 4096-block grid
// ran ~4.5 waves (6 resident blocks/SM) -> ~3.5 wave transitions of dead time.
// Now: __launch_bounds__(256,6) + grid = 152*6 = 912 blocks = exactly one
// wave, each warp grid-strides over ~36 rows. Keep R5 pair-unrolled loads
// (6 independent LDG.128 per iteration) and single-kernel last-block-done
// reduction with self-resetting ticket.

#define LOSS_WEIGHT 0.01f
#define N_SAMPLES 128
#define NUM_SMS 152
#define BLOCKS_PER_SM 6
#define GRID_BLOCKS (NUM_SMS * BLOCKS_PER_SM)   // 912
#define BLOCK_THREADS 256

__device__ double   g_partials[GRID_BLOCKS];
__device__ unsigned g_ticket = 0;   // self-resetting via atomicInc wrap

__device__ __forceinline__ float row_contrib(
    const float4 wv, const float4 mv, const float4 sv, const int lane)
{
    // uni term partial: sum s*w^2 over this lane's 4 elements
    float uni = sv.x * wv.x * wv.x;
    uni = fmaf(sv.y * wv.y, wv.y, uni);
    uni = fmaf(sv.z * wv.z, wv.z, uni);
    uni = fmaf(sv.w * wv.w, wv.w, uni);

    // wm = w * m
    const float wm0 = wv.x * mv.x;
    const float wm1 = wv.y * mv.y;
    const float wm2 = wv.z * mv.z;
    const float wm3 = wv.w * mv.w;

    // local exclusive prefixes within the 4-element chunk
    const float eW1 = wv.x;
    const float eW2 = eW1 + wv.y;
    const float eW3 = eW2 + wv.z;
    const float tW  = eW3 + wv.w;     // lane total of w

    const float eM1 = wm0;
    const float eM2 = eM1 + wm1;
    const float eM3 = eM2 + wm2;
    const float tM  = eM3 + wm3;      // lane total of wm

    // warp inclusive scan of lane totals (w and wm scanned together; the two
    // chains are independent so their SHFL latencies pipeline)
    float iW = tW, iM = tM;
    #pragma unroll
    for (int off = 1; off < 32; off <<= 1) {
        const float aW = __shfl_up_sync(0xffffffffu, iW, off);
        const float aM = __shfl_up_sync(0xffffffffu, iM, off);
        if (lane >= off) { iW += aW; iM += aM; }
    }
    const float EW = iW - tW;   // exclusive warp prefix of w
    const float EM = iM - tM;   // exclusive warp prefix of wm

    // bi term: sum_k wm_k * exW_k - w_k * exWM_k  (exclusive prefixes)
    float bi;
    bi  = wm0 * EW          - wv.x * EM;
    bi += wm1 * (EW + eW1)  - wv.y * (EM + eM1);
    bi += wm2 * (EW + eW2)  - wv.z * (EM + eM2);
    bi += wm3 * (EW + eW3)  - wv.w * (EM + eM3);

    return (1.0f / 3.0f) * uni + 2.0f * bi;
}

__global__ __launch_bounds__(BLOCK_THREADS, BLOCKS_PER_SM) void dl_fused_kernel(
    const float* __restrict__ w,
    const float* __restrict__ m,
    const float* __restrict__ s,
    float* __restrict__ out,
    int B, float scale)
{
    const int lane   = threadIdx.x & 31;
    const int warpIn = threadIdx.x >> 5;
    const int gwarp  = (blockIdx.x * BLOCK_THREADS + threadIdx.x) >> 5;
    const int nwarps = (gridDim.x * BLOCK_THREADS) >> 5;

    float acc = 0.0f;

    // Row-pair loop: warp handles rows (2g, 2g+1), stride 2*nwarps.
    int row = 2 * gwarp;
    for (; row + 1 < B; row += 2 * nwarps) {
        const size_t b0 = (size_t)row * N_SAMPLES;
        const size_t b1 = b0 + N_SAMPLES;
        // 6 independent 16B loads issued before any compute
        const float4 wv0 = reinterpret_cast<const float4*>(w + b0)[lane];
        const float4 wv1 = reinterpret_cast<const float4*>(w + b1)[lane];
        const float4 mv0 = reinterpret_cast<const float4*>(m + b0)[lane];
        const float4 mv1 = reinterpret_cast<const float4*>(m + b1)[lane];
        const float4 sv0 = reinterpret_cast<const float4*>(s + b0)[lane];
        const float4 sv1 = reinterpret_cast<const float4*>(s + b1)[lane];

        acc += row_contrib(wv0, mv0, sv0, lane);
        acc += row_contrib(wv1, mv1, sv1, lane);
    }
    if (row < B) {  // odd-B tail
        const size_t b0 = (size_t)row * N_SAMPLES;
        const float4 wv0 = reinterpret_cast<const float4*>(w + b0)[lane];
        const float4 mv0 = reinterpret_cast<const float4*>(m + b0)[lane];
        const float4 sv0 = reinterpret_cast<const float4*>(s + b0)[lane];
        acc += row_contrib(wv0, mv0, sv0, lane);
    }

    // warp reduce
    #pragma unroll
    for (int off = 16; off > 0; off >>= 1)
        acc += __shfl_down_sync(0xffffffffu, acc, off);

    __shared__ float warp_sums[BLOCK_THREADS / 32];
    if (lane == 0) warp_sums[warpIn] = acc;
    __syncthreads();

    __shared__ bool is_last;
    if (threadIdx.x == 0) {
        float blockAcc = 0.0f;
        #pragma unroll
        for (int i = 0; i < BLOCK_THREADS / 32; i++) blockAcc += warp_sums[i];
        g_partials[blockIdx.x] = (double)blockAcc;
        __threadfence();
        // atomicInc wraps to 0 after gridDim.x increments -> counter returns
        // to 0 at the end of every launch (no init kernel needed).
        const unsigned ticket = atomicInc(&g_ticket, gridDim.x - 1);
        is_last = (ticket == gridDim.x - 1);
    }
    __syncthreads();

    if (is_last) {
        __threadfence();
        double t = 0.0;
        for (int i = threadIdx.x; i < (int)gridDim.x; i += BLOCK_THREADS)
            t += g_partials[i];
        #pragma unroll
        for (int off = 16; off > 0; off >>= 1)
            t += __shfl_down_sync(0xffffffffu, t, off);
        __shared__ double dsums[BLOCK_THREADS / 32];
        if (lane == 0) dsums[warpIn] = t;
        __syncthreads();
        if (threadIdx.x == 0) {
            double total = 0.0;
            #pragma unroll
            for (int i = 0; i < BLOCK_THREADS / 32; i++) total += dsums[i];
            out[0] = (float)(total * (double)scale);
        }
    }
}

extern "C" void kernel_launch(void* const* d_in, const int* in_sizes, int n_in,
                              void* d_out, int out_size) {
    const float* w = (const float*)d_in[0];
    const float* m = (const float*)d_in[1];
    const float* s = (const float*)d_in[2];
    float* out = (float*)d_out;

    const int B = in_sizes[0] / N_SAMPLES;

    // Single persistent wave: 152 SMs x 6 blocks. Shrink only if B is tiny.
    int blocks = GRID_BLOCKS;
    const int warpsPerBlock = BLOCK_THREADS / 32;
    const int maxUseful = (B + 1) / 2;              // pairs of rows
    if (blocks * warpsPerBlock > maxUseful) {
        blocks = (maxUseful + warpsPerBlock - 1) / warpsPerBlock;
        if (blocks < 1) blocks = 1;
    }

    dl_fused_kernel<<<blocks, BLOCK_THREADS>>>(w, m, s, out, B,
                                               LOSS_WEIGHT / (float)B);
}

// round 7
// speedup vs baseline: 1.1005x; 1.1005x over previous
#include <cuda_runtime.h>
#include <cuda_bf16.h>

// DistortionLoss (eff_distloss) — two-kernel version, no init kernel.
//
// R6 -> R7: persistent single-wave regressed (straggler-bound); fused
// last-block-done never beat the R1 multi-kernel structure. New structure:
//   kernel 1 (hot): 4096 blocks x 256 thr, pair-unrolled streaming; each
//     block writes its partial UNCONDITIONALLY to g_partials[blockIdx]
//     (every slot written every launch -> no zeroing, no atomics, no fences,
//     no ticket, clean exit).
//   kernel 2: one block reduces the partials and writes the scalar.
// Main body keeps R5's 6 independent LDG.128 per iteration.

#define LOSS_WEIGHT 0.01f
#define N_SAMPLES 128
#define GRID_MAX 4096
#define BLOCK_THREADS 256

__device__ double g_partials[GRID_MAX];

__device__ __forceinline__ float row_contrib(
    const float4 wv, const float4 mv, const float4 sv, const int lane)
{
    // uni term partial: sum s*w^2 over this lane's 4 elements
    float uni = sv.x * wv.x * wv.x;
    uni = fmaf(sv.y * wv.y, wv.y, uni);
    uni = fmaf(sv.z * wv.z, wv.z, uni);
    uni = fmaf(sv.w * wv.w, wv.w, uni);

    // wm = w * m
    const float wm0 = wv.x * mv.x;
    const float wm1 = wv.y * mv.y;
    const float wm2 = wv.z * mv.z;
    const float wm3 = wv.w * mv.w;

    // local exclusive prefixes within the 4-element chunk
    const float eW1 = wv.x;
    const float eW2 = eW1 + wv.y;
    const float eW3 = eW2 + wv.z;
    const float tW  = eW3 + wv.w;     // lane total of w

    const float eM1 = wm0;
    const float eM2 = eM1 + wm1;
    const float eM3 = eM2 + wm2;
    const float tM  = eM3 + wm3;      // lane total of wm

    // warp inclusive scan of lane totals (w and wm together; independent
    // chains pipeline their SHFL latencies)
    float iW = tW, iM = tM;
    #pragma unroll
    for (int off = 1; off < 32; off <<= 1) {
        const float aW = __shfl_up_sync(0xffffffffu, iW, off);
        const float aM = __shfl_up_sync(0xffffffffu, iM, off);
        if (lane >= off) { iW += aW; iM += aM; }
    }
    const float EW = iW - tW;   // exclusive warp prefix of w
    const float EM = iM - tM;   // exclusive warp prefix of wm

    // bi term: sum_k wm_k * exW_k - w_k * exWM_k  (exclusive prefixes)
    float bi;
    bi  = wm0 * EW          - wv.x * EM;
    bi += wm1 * (EW + eW1)  - wv.y * (EM + eM1);
    bi += wm2 * (EW + eW2)  - wv.z * (EM + eM2);
    bi += wm3 * (EW + eW3)  - wv.w * (EM + eM3);

    return (1.0f / 3.0f) * uni + 2.0f * bi;
}

__global__ __launch_bounds__(BLOCK_THREADS) void dl_main_kernel(
    const float* __restrict__ w,
    const float* __restrict__ m,
    const float* __restrict__ s,
    int B)
{
    const int lane   = threadIdx.x & 31;
    const int warpIn = threadIdx.x >> 5;
    const int gwarp  = (blockIdx.x * BLOCK_THREADS + threadIdx.x) >> 5;
    const int nwarps = (gridDim.x * BLOCK_THREADS) >> 5;

    float acc = 0.0f;

    // Row-pair loop: warp handles rows (2g, 2g+1), stride 2*nwarps.
    int row = 2 * gwarp;
    for (; row + 1 < B; row += 2 * nwarps) {
        const size_t b0 = (size_t)row * N_SAMPLES;
        const size_t b1 = b0 + N_SAMPLES;
        // 6 independent 16B loads issued before any compute
        const float4 wv0 = reinterpret_cast<const float4*>(w + b0)[lane];
        const float4 wv1 = reinterpret_cast<const float4*>(w + b1)[lane];
        const float4 mv0 = reinterpret_cast<const float4*>(m + b0)[lane];
        const float4 mv1 = reinterpret_cast<const float4*>(m + b1)[lane];
        const float4 sv0 = reinterpret_cast<const float4*>(s + b0)[lane];
        const float4 sv1 = reinterpret_cast<const float4*>(s + b1)[lane];

        acc += row_contrib(wv0, mv0, sv0, lane);
        acc += row_contrib(wv1, mv1, sv1, lane);
    }
    if (row < B) {  // odd-B tail
        const size_t b0 = (size_t)row * N_SAMPLES;
        const float4 wv0 = reinterpret_cast<const float4*>(w + b0)[lane];
        const float4 mv0 = reinterpret_cast<const float4*>(m + b0)[lane];
        const float4 sv0 = reinterpret_cast<const float4*>(s + b0)[lane];
        acc += row_contrib(wv0, mv0, sv0, lane);
    }

    // warp reduce
    #pragma unroll
    for (int off = 16; off > 0; off >>= 1)
        acc += __shfl_down_sync(0xffffffffu, acc, off);

    __shared__ float warp_sums[BLOCK_THREADS / 32];
    if (lane == 0) warp_sums[warpIn] = acc;
    __syncthreads();

    if (threadIdx.x == 0) {
        float blockAcc = 0.0f;
        #pragma unroll
        for (int i = 0; i < BLOCK_THREADS / 32; i++) blockAcc += warp_sums[i];
        // Unconditional store: every launch writes every slot -> no init pass.
        g_partials[blockIdx.x] = (double)blockAcc;
    }
}

__global__ __launch_bounds__(BLOCK_THREADS) void dl_finalize_kernel(
    float* __restrict__ out, int nPartials, float scale)
{
    const int lane   = threadIdx.x & 31;
    const int warpIn = threadIdx.x >> 5;

    double t = 0.0;
    for (int i = threadIdx.x; i < nPartials; i += BLOCK_THREADS)
        t += g_partials[i];

    #pragma unroll
    for (int off = 16; off > 0; off >>= 1)
        t += __shfl_down_sync(0xffffffffu, t, off);

    __shared__ double dsums[BLOCK_THREADS / 32];
    if (lane == 0) dsums[warpIn] = t;
    __syncthreads();

    if (threadIdx.x == 0) {
        double total = 0.0;
        #pragma unroll
        for (int i = 0; i < BLOCK_THREADS / 32; i++) total += dsums[i];
        out[0] = (float)(total * (double)scale);
    }
}

extern "C" void kernel_launch(void* const* d_in, const int* in_sizes, int n_in,
                              void* d_out, int out_size) {
    const float* w = (const float*)d_in[0];
    const float* m = (const float*)d_in[1];
    const float* s = (const float*)d_in[2];
    float* out = (float*)d_out;

    const int B = in_sizes[0] / N_SAMPLES;

    const int warpsPerBlock = BLOCK_THREADS / 32;
    const int maxUseful = (B + 1) / 2;              // row pairs
    int blocks = GRID_MAX;
    if (blocks * warpsPerBlock > maxUseful) {
        blocks = (maxUseful + warpsPerBlock - 1) / warpsPerBlock;
        if (blocks < 1) blocks = 1;
    }

    dl_main_kernel<<<blocks, BLOCK_THREADS>>>(w, m, s, B);
    dl_finalize_kernel<<<1, BLOCK_THREADS>>>(out, blocks,
                                             LOSS_WEIGHT / (float)B);
}